// round 3
// baseline (speedup 1.0000x reference)
#include <cuda_runtime.h>

#define NW 12
#define NL 3
#define DIM 4096
#define NT 256

typedef unsigned long long ull;

__device__ __forceinline__ ull pk(float lo, float hi) {
    ull r; asm("mov.b64 %0,{%1,%2};" : "=l"(r) : "f"(lo), "f"(hi)); return r;
}
__device__ __forceinline__ void unpk(ull v, float& a, float& b) {
    asm("mov.b64 {%0,%1},%2;" : "=f"(a), "=f"(b) : "l"(v));
}
__device__ __forceinline__ ull mul2(ull a, ull b) {
    ull r; asm("mul.rn.f32x2 %0,%1,%2;" : "=l"(r) : "l"(a), "l"(b)); return r;
}
__device__ __forceinline__ ull fma2(ull a, ull b, ull c) {
    ull r; asm("fma.rn.f32x2 %0,%1,%2,%3;" : "=l"(r) : "l"(a), "l"(b), "l"(c)); return r;
}
__device__ __forceinline__ ull neg2(ull v) { return v ^ 0x8000000080000000ULL; }
__device__ __forceinline__ ull bclo(ull v) { float a, b; unpk(v, a, b); return pk(a, a); }
__device__ __forceinline__ ull bchi(ull v) { float a, b; unpk(v, a, b); return pk(b, b); }

// 16 amps per thread as 8 packed re + 8 packed im; pack dim = local bit 0.
// Local bit j corresponds to wire (wbase - j).
__device__ __forceinline__ void apply_group(ull par[8], ull pai[8],
                                            const float4 (*__restrict__ Usm)[2],
                                            int bg, int wbase)
{
    // ---- local bit 0 gate (pair lives inside the pack: lane-broadcast form) ----
    {
        float4 ua = Usm[bg + wbase][0];
        float4 ub = Usm[bg + wbase][1];
        ull CA = pk(ua.x, ub.x), CB = pk(ua.y, ub.y), CBn = pk(-ua.y, -ub.y);
        ull CC = pk(ua.z, ub.z), CD = pk(ua.w, ub.w), CDn = pk(-ua.w, -ub.w);
#pragma unroll
        for (int m = 0; m < 8; m++) {
            ull R0b = bclo(par[m]), R1b = bchi(par[m]);
            ull Q0b = bclo(pai[m]), Q1b = bchi(pai[m]);
            par[m] = fma2(CA, R0b, fma2(CBn, Q0b, fma2(CC, R1b, mul2(CDn, Q1b))));
            pai[m] = fma2(CA, Q0b, fma2(CB, R0b, fma2(CC, Q1b, mul2(CD, R1b))));
        }
    }
    // ---- local bits 1..3: clean packed pair gates ----
#pragma unroll
    for (int jj = 1; jj < 4; jj++) {
        float4 ua = Usm[bg + (wbase - jj)][0];
        float4 ub = Usm[bg + (wbase - jj)][1];
        ull A0r = pk(ua.x, ua.x), A0i = pk(ua.y, ua.y);
        ull A1r = pk(ua.z, ua.z), A1i = pk(ua.w, ua.w);
        ull B0r = pk(ub.x, ub.x), B0i = pk(ub.y, ub.y);
        ull B1r = pk(ub.z, ub.z), B1i = pk(ub.w, ub.w);
        const int jp = jj - 1;
#pragma unroll
        for (int p = 0; p < 4; p++) {
            int m0 = ((p >> jp) << (jp + 1)) | (p & ((1 << jp) - 1));
            int m1 = m0 | (1 << jp);
            ull R0 = par[m0], Q0 = pai[m0], R1 = par[m1], Q1 = pai[m1];
            ull Q0n = neg2(Q0), Q1n = neg2(Q1);
            par[m0] = fma2(A0r, R0, fma2(A0i, Q0n, fma2(A1r, R1, mul2(A1i, Q1n))));
            pai[m0] = fma2(A0r, Q0, fma2(A0i, R0, fma2(A1r, Q1, mul2(A1i, R1))));
            par[m1] = fma2(B0r, R0, fma2(B0i, Q0n, fma2(B1r, R1, mul2(B1i, Q1n))));
            pai[m1] = fma2(B0r, Q0, fma2(B0i, R0, fma2(B1r, Q1, mul2(B1i, R1))));
        }
    }
}

__global__ __launch_bounds__(NT, 4)
void qsim_kernel(const float* __restrict__ state,
                 const float* __restrict__ weights,
                 const float* __restrict__ head_w,
                 const float* __restrict__ head_b,
                 float* __restrict__ out)
{
    __shared__ float sre[DIM + DIM / 16];  // 4352 floats, pad every 16
    __shared__ float sim[DIM + DIM / 16];
    __shared__ float4 Usm[NL * NW][2];
    __shared__ float hw[NW];
    __shared__ float warpsum[NT / 32];

    const int tid = threadIdx.x;
    const int b = blockIdx.x;

    // ---- gate matrices U = RZ(c) RY(b) RX(a) ----
    if (tid < NL * NW) {
        float a = weights[tid * 3 + 0];
        float bb = weights[tid * 3 + 1];
        float c = weights[tid * 3 + 2];
        float sa, ca, sb, cb, sc, cc;
        sincosf(0.5f * a, &sa, &ca);
        sincosf(0.5f * bb, &sb, &cb);
        sincosf(0.5f * c, &sc, &cc);
        float m00r = cb * ca, m00i = sb * sa;
        float m01r = -sb * ca, m01i = -cb * sa;
        float m10r = sb * ca, m10i = -cb * sa;
        float m11r = cb * ca, m11i = -sb * sa;
        float4 ua, ub;
        ua.x = m00r * cc + m00i * sc;  ua.y = m00i * cc - m00r * sc;
        ua.z = m01r * cc + m01i * sc;  ua.w = m01i * cc - m01r * sc;
        ub.x = m10r * cc - m10i * sc;  ub.y = m10i * cc + m10r * sc;
        ub.z = m11r * cc - m11i * sc;  ub.w = m11i * cc + m11r * sc;
        Usm[tid][0] = ua;
        Usm[tid][1] = ub;
    }
    if (tid < NW) hw[tid] = head_w[tid];

    // ---- load state (mapping A: i = (tid<<4)|k), pack adjacent amps ----
    ull par[8], pai[8];
    const float4* st4 = (const float4*)(state + (size_t)b * DIM);
#pragma unroll
    for (int q = 0; q < 4; q++) {
        float4 v = st4[tid * 4 + q];
        par[2 * q + 0] = pk(v.x, v.y);
        par[2 * q + 1] = pk(v.z, v.w);
        pai[2 * q + 0] = 0ULL;
        pai[2 * q + 1] = 0ULL;
    }
    __syncthreads();  // Usm / hw ready

    for (int l = 0; l < NL; l++) {
        const int bg = l * NW;

        // group A: index bits 0-3 local -> wires 11..8
        apply_group(par, pai, Usm, bg, 11);

        // remap A -> B
        __syncthreads();
#pragma unroll
        for (int m = 0; m < 8; m++) {
            float r0, r1, q0, q1;
            unpk(par[m], r0, r1); unpk(pai[m], q0, q1);
            int s0 = tid * 17 + 2 * m;
            sre[s0] = r0; sre[s0 + 1] = r1;
            sim[s0] = q0; sim[s0 + 1] = q1;
        }
        __syncthreads();
#pragma unroll
        for (int m = 0; m < 8; m++) {
            int base = ((tid >> 4) << 8) | (tid & 15);
            int i0 = base | ((2 * m) << 4);
            int i1 = base | ((2 * m + 1) << 4);
            int s0 = i0 + (i0 >> 4), s1 = i1 + (i1 >> 4);
            par[m] = pk(sre[s0], sre[s1]);
            pai[m] = pk(sim[s0], sim[s1]);
        }

        // group B: index bits 4-7 local -> wires 7..4
        apply_group(par, pai, Usm, bg, 7);

        // remap B -> C
        __syncthreads();
#pragma unroll
        for (int m = 0; m < 8; m++) {
            float r0, r1, q0, q1;
            unpk(par[m], r0, r1); unpk(pai[m], q0, q1);
            int base = ((tid >> 4) << 8) | (tid & 15);
            int i0 = base | ((2 * m) << 4);
            int i1 = base | ((2 * m + 1) << 4);
            int s0 = i0 + (i0 >> 4), s1 = i1 + (i1 >> 4);
            sre[s0] = r0; sre[s1] = r1;
            sim[s0] = q0; sim[s1] = q1;
        }
        __syncthreads();
#pragma unroll
        for (int m = 0; m < 8; m++) {
            int i0 = ((2 * m) << 8) | tid;
            int i1 = ((2 * m + 1) << 8) | tid;
            int s0 = i0 + (i0 >> 4), s1 = i1 + (i1 >> 4);
            par[m] = pk(sre[s0], sre[s1]);
            pai[m] = pk(sim[s0], sim[s1]);
        }

        // group C: index bits 8-11 local -> wires 3..0
        apply_group(par, pai, Usm, bg, 3);

        // layer boundary: remap C -> A fused with CNOT chain perm
        // psi_new[y] = psi_old[y ^ (y>>1)]
        if (l < NL - 1) {
            __syncthreads();
#pragma unroll
            for (int m = 0; m < 8; m++) {
                float r0, r1, q0, q1;
                unpk(par[m], r0, r1); unpk(pai[m], q0, q1);
                int i0 = ((2 * m) << 8) | tid;
                int i1 = ((2 * m + 1) << 8) | tid;
                int s0 = i0 + (i0 >> 4), s1 = i1 + (i1 >> 4);
                sre[s0] = r0; sre[s1] = r1;
                sim[s0] = q0; sim[s1] = q1;
            }
            __syncthreads();
#pragma unroll
            for (int m = 0; m < 8; m++) {
                int y0 = (tid << 4) | (2 * m);
                int y1 = y0 | 1;
                int src0 = y0 ^ (y0 >> 1);
                int src1 = y1 ^ (y1 >> 1);
                int s0 = src0 + (src0 >> 4), s1 = src1 + (src1 >> 4);
                par[m] = pk(sre[s0], sre[s1]);
                pai[m] = pk(sim[s0], sim[s1]);
            }
        }
    }

    // ---- measurement (mapping C regs), last CNOT perm folded into weights ----
    // out = sum_x |psi[x]|^2 * c(prefixXOR(x)) + bias ; x = (k<<8)|tid
    int m8 = tid;
    m8 ^= m8 >> 1; m8 ^= m8 >> 2; m8 ^= m8 >> 4;  // suffix-XOR over 8 bits
    float c_low = 0.f;
#pragma unroll
    for (int w = 4; w < 12; w++) {
        c_low += ((m8 >> (11 - w)) & 1) ? -hw[w] : hw[w];
    }
    float acc = 0.f;
#pragma unroll
    for (int m = 0; m < 8; m++) {
        float r0, r1, q0, q1;
        unpk(par[m], r0, r1); unpk(pai[m], q0, q1);
#pragma unroll
        for (int s = 0; s < 2; s++) {
            int k = 2 * m + s;
            int g4 = k;
            g4 ^= g4 >> 1; g4 ^= g4 >> 2;  // suffix-XOR over 4 bits
            float c_high = 0.f;
#pragma unroll
            for (int w = 0; w < 4; w++) {
                c_high += ((g4 >> (3 - w)) & 1) ? -hw[w] : hw[w];
            }
            float c = c_high + ((g4 & 1) ? -c_low : c_low);
            float rr = s ? r1 : r0;
            float qq = s ? q1 : q0;
            acc += (rr * rr + qq * qq) * c;
        }
    }
#pragma unroll
    for (int o = 16; o > 0; o >>= 1)
        acc += __shfl_xor_sync(0xffffffffu, acc, o);
    if ((tid & 31) == 0) warpsum[tid >> 5] = acc;
    __syncthreads();
    if (tid == 0) {
        float s = 0.f;
#pragma unroll
        for (int i = 0; i < NT / 32; i++) s += warpsum[i];
        out[b] = s + head_b[0];
    }
}

extern "C" void kernel_launch(void* const* d_in, const int* in_sizes, int n_in,
                              void* d_out, int out_size)
{
    const float* state   = (const float*)d_in[0];  // (512, 4096)
    const float* weights = (const float*)d_in[1];  // (3, 12, 3)
    const float* head_w  = (const float*)d_in[2];  // (1, 12)
    const float* head_b  = (const float*)d_in[3];  // (1,)
    float* out = (float*)d_out;                    // (512,)
    qsim_kernel<<<512, NT>>>(state, weights, head_w, head_b, out);
}

// round 4
// speedup vs baseline: 1.0496x; 1.0496x over previous
#include <cuda_runtime.h>

#define NW 12
#define NL 3
#define DIM 4096
#define NT 256

typedef unsigned long long ull;

__device__ __forceinline__ ull pk(float lo, float hi) {
    ull r; asm("mov.b64 %0,{%1,%2};" : "=l"(r) : "f"(lo), "f"(hi)); return r;
}
__device__ __forceinline__ void unpk(ull v, float& a, float& b) {
    asm("mov.b64 {%0,%1},%2;" : "=f"(a), "=f"(b) : "l"(v));
}
__device__ __forceinline__ ull mul2(ull a, ull b) {
    ull r; asm("mul.rn.f32x2 %0,%1,%2;" : "=l"(r) : "l"(a), "l"(b)); return r;
}
__device__ __forceinline__ ull fma2(ull a, ull b, ull c) {
    ull r; asm("fma.rn.f32x2 %0,%1,%2,%3;" : "=l"(r) : "l"(a), "l"(b), "l"(c)); return r;
}
__device__ __forceinline__ ull neg2(ull v) { return v ^ 0x8000000080000000ULL; }
__device__ __forceinline__ ull bclo(ull v) { float a, b; unpk(v, a, b); return pk(a, a); }
__device__ __forceinline__ ull bchi(ull v) { float a, b; unpk(v, a, b); return pk(b, b); }

// 16 amps per thread as 8 packed re + 8 packed im; pack dim = local bit 0.
// Local bit j corresponds to wire (wbase - j).
__device__ __forceinline__ void apply_group(ull par[8], ull pai[8],
                                            const float4 (*__restrict__ Usm)[2],
                                            int bg, int wbase)
{
    // ---- local bit 0 gate (pair lives inside the pack: lane-broadcast form) ----
    {
        float4 ua = Usm[bg + wbase][0];
        float4 ub = Usm[bg + wbase][1];
        ull CA = pk(ua.x, ub.x), CB = pk(ua.y, ub.y), CBn = pk(-ua.y, -ub.y);
        ull CC = pk(ua.z, ub.z), CD = pk(ua.w, ub.w), CDn = pk(-ua.w, -ub.w);
#pragma unroll
        for (int m = 0; m < 8; m++) {
            ull R0b = bclo(par[m]), R1b = bchi(par[m]);
            ull Q0b = bclo(pai[m]), Q1b = bchi(pai[m]);
            par[m] = fma2(CA, R0b, fma2(CBn, Q0b, fma2(CC, R1b, mul2(CDn, Q1b))));
            pai[m] = fma2(CA, Q0b, fma2(CB, R0b, fma2(CC, Q1b, mul2(CD, R1b))));
        }
    }
    // ---- local bits 1..3: clean packed pair gates ----
#pragma unroll
    for (int jj = 1; jj < 4; jj++) {
        float4 ua = Usm[bg + (wbase - jj)][0];
        float4 ub = Usm[bg + (wbase - jj)][1];
        ull A0r = pk(ua.x, ua.x), A0i = pk(ua.y, ua.y);
        ull A1r = pk(ua.z, ua.z), A1i = pk(ua.w, ua.w);
        ull B0r = pk(ub.x, ub.x), B0i = pk(ub.y, ub.y);
        ull B1r = pk(ub.z, ub.z), B1i = pk(ub.w, ub.w);
        const int jp = jj - 1;
#pragma unroll
        for (int p = 0; p < 4; p++) {
            int m0 = ((p >> jp) << (jp + 1)) | (p & ((1 << jp) - 1));
            int m1 = m0 | (1 << jp);
            ull R0 = par[m0], Q0 = pai[m0], R1 = par[m1], Q1 = pai[m1];
            ull Q0n = neg2(Q0), Q1n = neg2(Q1);
            par[m0] = fma2(A0r, R0, fma2(A0i, Q0n, fma2(A1r, R1, mul2(A1i, Q1n))));
            pai[m0] = fma2(A0r, Q0, fma2(A0i, R0, fma2(A1r, Q1, mul2(A1i, R1))));
            par[m1] = fma2(B0r, R0, fma2(B0i, Q0n, fma2(B1r, R1, mul2(B1i, Q1n))));
            pai[m1] = fma2(B0r, Q0, fma2(B0i, R0, fma2(B1r, Q1, mul2(B1i, R1))));
        }
    }
}

__global__ __launch_bounds__(NT, 4)
void qsim_kernel(const float* __restrict__ state,
                 const float* __restrict__ weights,
                 const float* __restrict__ head_w,
                 const float* __restrict__ head_b,
                 float* __restrict__ out)
{
    __shared__ float sre[DIM + DIM / 16];  // 4352 floats, pad every 16
    __shared__ float sim[DIM + DIM / 16];
    __shared__ float4 Usm[NL * NW][2];
    __shared__ float hw[NW];
    __shared__ float warpsum[NT / 32];

    const int tid = threadIdx.x;
    const int b = blockIdx.x;

    // ---- gate matrices U = RZ(c) RY(b) RX(a) ----
    if (tid < NL * NW) {
        float a = weights[tid * 3 + 0];
        float bb = weights[tid * 3 + 1];
        float c = weights[tid * 3 + 2];
        float sa, ca, sb, cb, sc, cc;
        sincosf(0.5f * a, &sa, &ca);
        sincosf(0.5f * bb, &sb, &cb);
        sincosf(0.5f * c, &sc, &cc);
        float m00r = cb * ca, m00i = sb * sa;
        float m01r = -sb * ca, m01i = -cb * sa;
        float m10r = sb * ca, m10i = -cb * sa;
        float m11r = cb * ca, m11i = -sb * sa;
        float4 ua, ub;
        ua.x = m00r * cc + m00i * sc;  ua.y = m00i * cc - m00r * sc;
        ua.z = m01r * cc + m01i * sc;  ua.w = m01i * cc - m01r * sc;
        ub.x = m10r * cc - m10i * sc;  ub.y = m10i * cc + m10r * sc;
        ub.z = m11r * cc - m11i * sc;  ub.w = m11i * cc + m11r * sc;
        Usm[tid][0] = ua;
        Usm[tid][1] = ub;
    }
    if (tid < NW) hw[tid] = head_w[tid];

    // ---- load state (mapping A: i = (tid<<4)|k), pack adjacent amps ----
    ull par[8], pai[8];
    const float4* st4 = (const float4*)(state + (size_t)b * DIM);
#pragma unroll
    for (int q = 0; q < 4; q++) {
        float4 v = st4[tid * 4 + q];
        par[2 * q + 0] = pk(v.x, v.y);
        par[2 * q + 1] = pk(v.z, v.w);
        pai[2 * q + 0] = 0ULL;
        pai[2 * q + 1] = 0ULL;
    }
    __syncthreads();  // Usm / hw ready

    for (int l = 0; l < NL; l++) {
        const int bg = l * NW;

        // group A: index bits 0-3 local -> wires 11..8
        apply_group(par, pai, Usm, bg, 11);

        // remap A -> B
        __syncthreads();
#pragma unroll
        for (int m = 0; m < 8; m++) {
            float r0, r1, q0, q1;
            unpk(par[m], r0, r1); unpk(pai[m], q0, q1);
            int s0 = tid * 17 + 2 * m;
            sre[s0] = r0; sre[s0 + 1] = r1;
            sim[s0] = q0; sim[s0 + 1] = q1;
        }
        __syncthreads();
#pragma unroll
        for (int m = 0; m < 8; m++) {
            int base = ((tid >> 4) << 8) | (tid & 15);
            int i0 = base | ((2 * m) << 4);
            int i1 = base | ((2 * m + 1) << 4);
            int s0 = i0 + (i0 >> 4), s1 = i1 + (i1 >> 4);
            par[m] = pk(sre[s0], sre[s1]);
            pai[m] = pk(sim[s0], sim[s1]);
        }

        // group B: index bits 4-7 local -> wires 7..4
        apply_group(par, pai, Usm, bg, 7);

        // remap B -> C
        __syncthreads();
#pragma unroll
        for (int m = 0; m < 8; m++) {
            float r0, r1, q0, q1;
            unpk(par[m], r0, r1); unpk(pai[m], q0, q1);
            int base = ((tid >> 4) << 8) | (tid & 15);
            int i0 = base | ((2 * m) << 4);
            int i1 = base | ((2 * m + 1) << 4);
            int s0 = i0 + (i0 >> 4), s1 = i1 + (i1 >> 4);
            sre[s0] = r0; sre[s1] = r1;
            sim[s0] = q0; sim[s1] = q1;
        }
        __syncthreads();
#pragma unroll
        for (int m = 0; m < 8; m++) {
            int i0 = ((2 * m) << 8) | tid;
            int i1 = ((2 * m + 1) << 8) | tid;
            int s0 = i0 + (i0 >> 4), s1 = i1 + (i1 >> 4);
            par[m] = pk(sre[s0], sre[s1]);
            pai[m] = pk(sim[s0], sim[s1]);
        }

        // group C: index bits 8-11 local -> wires 3..0
        apply_group(par, pai, Usm, bg, 3);

        // layer boundary: remap C -> A fused with CNOT chain perm
        // psi_new[y] = psi_old[y ^ (y>>1)]
        if (l < NL - 1) {
            __syncthreads();
#pragma unroll
            for (int m = 0; m < 8; m++) {
                float r0, r1, q0, q1;
                unpk(par[m], r0, r1); unpk(pai[m], q0, q1);
                int i0 = ((2 * m) << 8) | tid;
                int i1 = ((2 * m + 1) << 8) | tid;
                int s0 = i0 + (i0 >> 4), s1 = i1 + (i1 >> 4);
                sre[s0] = r0; sre[s1] = r1;
                sim[s0] = q0; sim[s1] = q1;
            }
            __syncthreads();
#pragma unroll
            for (int m = 0; m < 8; m++) {
                int y0 = (tid << 4) | (2 * m);
                int y1 = y0 | 1;
                int src0 = y0 ^ (y0 >> 1);
                int src1 = y1 ^ (y1 >> 1);
                int s0 = src0 + (src0 >> 4), s1 = src1 + (src1 >> 4);
                par[m] = pk(sre[s0], sre[s1]);
                pai[m] = pk(sim[s0], sim[s1]);
            }
        }
    }

    // ---- measurement (mapping C regs), last CNOT perm folded into weights ----
    // out = sum_x |psi[x]|^2 * c(prefixXOR(x)) + bias ; x = (k<<8)|tid
    int m8 = tid;
    m8 ^= m8 >> 1; m8 ^= m8 >> 2; m8 ^= m8 >> 4;  // suffix-XOR over 8 bits
    float c_low = 0.f;
#pragma unroll
    for (int w = 4; w < 12; w++) {
        c_low += ((m8 >> (11 - w)) & 1) ? -hw[w] : hw[w];
    }
    float acc = 0.f;
#pragma unroll
    for (int m = 0; m < 8; m++) {
        float r0, r1, q0, q1;
        unpk(par[m], r0, r1); unpk(pai[m], q0, q1);
#pragma unroll
        for (int s = 0; s < 2; s++) {
            int k = 2 * m + s;
            int g4 = k;
            g4 ^= g4 >> 1; g4 ^= g4 >> 2;  // suffix-XOR over 4 bits
            float c_high = 0.f;
#pragma unroll
            for (int w = 0; w < 4; w++) {
                c_high += ((g4 >> (3 - w)) & 1) ? -hw[w] : hw[w];
            }
            float c = c_high + ((g4 & 1) ? -c_low : c_low);
            float rr = s ? r1 : r0;
            float qq = s ? q1 : q0;
            acc += (rr * rr + qq * qq) * c;
        }
    }
#pragma unroll
    for (int o = 16; o > 0; o >>= 1)
        acc += __shfl_xor_sync(0xffffffffu, acc, o);
    if ((tid & 31) == 0) warpsum[tid >> 5] = acc;
    __syncthreads();
    if (tid == 0) {
        float s = 0.f;
#pragma unroll
        for (int i = 0; i < NT / 32; i++) s += warpsum[i];
        out[b] = s + head_b[0];
    }
}

extern "C" void kernel_launch(void* const* d_in, const int* in_sizes, int n_in,
                              void* d_out, int out_size)
{
    const float* state   = (const float*)d_in[0];  // (512, 4096)
    const float* weights = (const float*)d_in[1];  // (3, 12, 3)
    const float* head_w  = (const float*)d_in[2];  // (1, 12)
    const float* head_b  = (const float*)d_in[3];  // (1,)
    float* out = (float*)d_out;                    // (512,)
    qsim_kernel<<<512, NT>>>(state, weights, head_w, head_b, out);
}

// round 5
// speedup vs baseline: 1.1729x; 1.1175x over previous
#include <cuda_runtime.h>

#define NW 12
#define NL 3
#define DIM 4096
#define BATCH 512
#define NT 256
#define PADDED (DIM + DIM / 16)              // 4352
#define DYN_SMEM (2 * PADDED * 8)            // 69,632 B (re + im, ull each)

typedef unsigned long long ull;

__device__ __forceinline__ ull pk(float lo, float hi) {
    ull r; asm("mov.b64 %0,{%1,%2};" : "=l"(r) : "f"(lo), "f"(hi)); return r;
}
__device__ __forceinline__ void unpk(ull v, float& a, float& b) {
    asm("mov.b64 {%0,%1},%2;" : "=f"(a), "=f"(b) : "l"(v));
}
__device__ __forceinline__ ull mul2(ull a, ull b) {
    ull r; asm("mul.rn.f32x2 %0,%1,%2;" : "=l"(r) : "l"(a), "l"(b)); return r;
}
__device__ __forceinline__ ull fma2(ull a, ull b, ull c) {
    ull r; asm("fma.rn.f32x2 %0,%1,%2,%3;" : "=l"(r) : "l"(a), "l"(b), "l"(c)); return r;
}

// pad every 16 -> conflict-free remap phases
__device__ __forceinline__ int pidx(int i) { return i + (i >> 4); }

// 16 packed amps (2 batch elems per pack). Local bit j <-> wire (wbase - j).
// All gates are clean packed-pair gates: zero per-pair ALU overhead.
__device__ __forceinline__ void apply_group(ull ar[16], ull ai[16],
                                            const float4 (*__restrict__ Usm)[2],
                                            int bg, int wbase)
{
#pragma unroll
    for (int j = 0; j < 4; j++) {
        float4 ua = Usm[bg + (wbase - j)][0];  // u00r,u00i,u01r,u01i
        float4 ub = Usm[bg + (wbase - j)][1];  // u10r,u10i,u11r,u11i
        ull A0r = pk(ua.x, ua.x), A0i = pk(ua.y, ua.y), A0in = pk(-ua.y, -ua.y);
        ull A1r = pk(ua.z, ua.z), A1i = pk(ua.w, ua.w), A1in = pk(-ua.w, -ua.w);
        ull B0r = pk(ub.x, ub.x), B0i = pk(ub.y, ub.y), B0in = pk(-ub.y, -ub.y);
        ull B1r = pk(ub.z, ub.z), B1i = pk(ub.w, ub.w), B1in = pk(-ub.w, -ub.w);
#pragma unroll
        for (int p = 0; p < 8; p++) {
            int k0 = ((p >> j) << (j + 1)) | (p & ((1 << j) - 1));
            int k1 = k0 | (1 << j);
            ull R0 = ar[k0], Q0 = ai[k0], R1 = ar[k1], Q1 = ai[k1];
            ar[k0] = fma2(A0r, R0, fma2(A0in, Q0, fma2(A1r, R1, mul2(A1in, Q1))));
            ai[k0] = fma2(A0r, Q0, fma2(A0i,  R0, fma2(A1r, Q1, mul2(A1i,  R1))));
            ar[k1] = fma2(B0r, R0, fma2(B0in, Q0, fma2(B1r, R1, mul2(B1in, Q1))));
            ai[k1] = fma2(B0r, Q0, fma2(B0i,  R0, fma2(B1r, Q1, mul2(B1i,  R1))));
        }
    }
}

__global__ __launch_bounds__(NT, 2)
void qsim_kernel(const float* __restrict__ state,
                 const float* __restrict__ weights,
                 const float* __restrict__ head_w,
                 const float* __restrict__ head_b,
                 float* __restrict__ out)
{
    extern __shared__ ull dyn[];
    ull* bre = dyn;            // [PADDED]
    ull* bim = dyn + PADDED;   // [PADDED]
    __shared__ float4 Usm[NL * NW][2];
    __shared__ float hw[NW];
    __shared__ ull warpsum[NT / 32];

    const int tid = threadIdx.x;
    const int b = blockIdx.x;  // handles batch rows 2b, 2b+1

    // ---- gate matrices U = RZ(c) RY(b) RX(a) ----
    if (tid < NL * NW) {
        float a = weights[tid * 3 + 0];
        float bb = weights[tid * 3 + 1];
        float c = weights[tid * 3 + 2];
        float sa, ca, sb, cb, sc, cc;
        sincosf(0.5f * a, &sa, &ca);
        sincosf(0.5f * bb, &sb, &cb);
        sincosf(0.5f * c, &sc, &cc);
        float m00r = cb * ca, m00i = sb * sa;
        float m01r = -sb * ca, m01i = -cb * sa;
        float m10r = sb * ca, m10i = -cb * sa;
        float m11r = cb * ca, m11i = -sb * sa;
        float4 uA, uB;
        uA.x = m00r * cc + m00i * sc;  uA.y = m00i * cc - m00r * sc;
        uA.z = m01r * cc + m01i * sc;  uA.w = m01i * cc - m01r * sc;
        uB.x = m10r * cc - m10i * sc;  uB.y = m10i * cc + m10r * sc;
        uB.z = m11r * cc - m11i * sc;  uB.w = m11i * cc + m11r * sc;
        Usm[tid][0] = uA;
        Usm[tid][1] = uB;
    }
    if (tid < NW) hw[tid] = head_w[tid];

    // ---- load two batch rows, pack into lanes (mapping A: i = (tid<<4)|k) ----
    ull ar[16], ai[16];
    const float4* s0 = (const float4*)(state + (size_t)(2 * b) * DIM);
    const float4* s1 = (const float4*)(state + (size_t)(2 * b + 1) * DIM);
#pragma unroll
    for (int q = 0; q < 4; q++) {
        float4 v0 = s0[tid * 4 + q];
        float4 v1 = s1[tid * 4 + q];
        ar[4 * q + 0] = pk(v0.x, v1.x);
        ar[4 * q + 1] = pk(v0.y, v1.y);
        ar[4 * q + 2] = pk(v0.z, v1.z);
        ar[4 * q + 3] = pk(v0.w, v1.w);
        ai[4 * q + 0] = 0ULL; ai[4 * q + 1] = 0ULL;
        ai[4 * q + 2] = 0ULL; ai[4 * q + 3] = 0ULL;
    }
    __syncthreads();  // Usm / hw ready

    for (int l = 0; l < NL; l++) {
        const int bg = l * NW;

        // group A: index bits 0-3 local -> wires 11..8
        apply_group(ar, ai, Usm, bg, 11);

        // remap A -> B
        __syncthreads();
#pragma unroll
        for (int k = 0; k < 16; k++) {
            int s = tid * 17 + k;          // pidx((tid<<4)|k)
            bre[s] = ar[k];
            bim[s] = ai[k];
        }
        __syncthreads();
#pragma unroll
        for (int k = 0; k < 16; k++) {
            int i = ((tid >> 4) << 8) | (k << 4) | (tid & 15);
            int s = pidx(i);
            ar[k] = bre[s];
            ai[k] = bim[s];
        }

        // group B: index bits 4-7 local -> wires 7..4
        apply_group(ar, ai, Usm, bg, 7);

        // remap B -> C
        __syncthreads();
#pragma unroll
        for (int k = 0; k < 16; k++) {
            int i = ((tid >> 4) << 8) | (k << 4) | (tid & 15);
            int s = pidx(i);
            bre[s] = ar[k];
            bim[s] = ai[k];
        }
        __syncthreads();
#pragma unroll
        for (int k = 0; k < 16; k++) {
            int i = (k << 8) | tid;
            int s = pidx(i);
            ar[k] = bre[s];
            ai[k] = bim[s];
        }

        // group C: index bits 8-11 local -> wires 3..0
        apply_group(ar, ai, Usm, bg, 3);

        // layer boundary: remap C -> A fused with CNOT-chain perm
        // psi_new[y] = psi_old[y ^ (y>>1)]
        if (l < NL - 1) {
            __syncthreads();
#pragma unroll
            for (int k = 0; k < 16; k++) {
                int i = (k << 8) | tid;
                int s = pidx(i);
                bre[s] = ar[k];
                bim[s] = ai[k];
            }
            __syncthreads();
#pragma unroll
            for (int k = 0; k < 16; k++) {
                int y = (tid << 4) | k;
                int src = y ^ (y >> 1);
                int s = pidx(src);
                ar[k] = bre[s];
                ai[k] = bim[s];
            }
        }
    }

    // ---- measurement (mapping C), last CNOT perm folded into weights ----
    // out = sum_x |psi[x]|^2 * c(prefixXOR(x)) + bias ; x = (k<<8)|tid
    int m8 = tid;
    m8 ^= m8 >> 1; m8 ^= m8 >> 2; m8 ^= m8 >> 4;  // suffix-XOR over 8 bits
    float c_low = 0.f;
#pragma unroll
    for (int w = 4; w < 12; w++) {
        c_low += ((m8 >> (11 - w)) & 1) ? -hw[w] : hw[w];
    }
    ull acc2 = 0ULL;
#pragma unroll
    for (int k = 0; k < 16; k++) {
        int g4 = k;
        g4 ^= g4 >> 1; g4 ^= g4 >> 2;  // suffix-XOR over 4 bits
        float c_high = 0.f;
#pragma unroll
        for (int w = 0; w < 4; w++) {
            c_high += ((g4 >> (3 - w)) & 1) ? -hw[w] : hw[w];
        }
        float c = c_high + ((g4 & 1) ? -c_low : c_low);
        ull pr2 = fma2(ar[k], ar[k], mul2(ai[k], ai[k]));  // |psi|^2 both lanes
        acc2 = fma2(pr2, pk(c, c), acc2);
    }
#pragma unroll
    for (int o = 16; o > 0; o >>= 1) {
        float lo, hi;
        unpk(acc2, lo, hi);
        lo += __shfl_xor_sync(0xffffffffu, lo, o);
        hi += __shfl_xor_sync(0xffffffffu, hi, o);
        acc2 = pk(lo, hi);
    }
    if ((tid & 31) == 0) warpsum[tid >> 5] = acc2;
    __syncthreads();
    if (tid == 0) {
        float slo = 0.f, shi = 0.f;
#pragma unroll
        for (int i = 0; i < NT / 32; i++) {
            float lo, hi;
            unpk(warpsum[i], lo, hi);
            slo += lo; shi += hi;
        }
        float bias = head_b[0];
        out[2 * b + 0] = slo + bias;
        out[2 * b + 1] = shi + bias;
    }
}

extern "C" void kernel_launch(void* const* d_in, const int* in_sizes, int n_in,
                              void* d_out, int out_size)
{
    const float* state   = (const float*)d_in[0];  // (512, 4096)
    const float* weights = (const float*)d_in[1];  // (3, 12, 3)
    const float* head_w  = (const float*)d_in[2];  // (1, 12)
    const float* head_b  = (const float*)d_in[3];  // (1,)
    float* out = (float*)d_out;                    // (512,)
    cudaFuncSetAttribute(qsim_kernel, cudaFuncAttributeMaxDynamicSharedMemorySize, DYN_SMEM);
    qsim_kernel<<<BATCH / 2, NT, DYN_SMEM>>>(state, weights, head_w, head_b, out);
}

// round 6
// speedup vs baseline: 1.1819x; 1.0077x over previous
#include <cuda_runtime.h>

#define NW 12
#define NL 3
#define DIM 4096
#define BATCH 512
#define NT 256
#define PADDED (DIM + DIM / 16)          // 4352 elements
#define DYN_SMEM (PADDED * 16)           // 69,632 B of ulonglong2 {re,im}

typedef unsigned long long ull;

__device__ __forceinline__ ull pk(float lo, float hi) {
    ull r; asm("mov.b64 %0,{%1,%2};" : "=l"(r) : "f"(lo), "f"(hi)); return r;
}
__device__ __forceinline__ void unpk(ull v, float& a, float& b) {
    asm("mov.b64 {%0,%1},%2;" : "=f"(a), "=f"(b) : "l"(v));
}
__device__ __forceinline__ ull mul2(ull a, ull b) {
    ull r; asm("mul.rn.f32x2 %0,%1,%2;" : "=l"(r) : "l"(a), "l"(b)); return r;
}
__device__ __forceinline__ ull fma2(ull a, ull b, ull c) {
    ull r; asm("fma.rn.f32x2 %0,%1,%2,%3;" : "=l"(r) : "l"(a), "l"(b), "l"(c)); return r;
}
__device__ __forceinline__ ull neg2(ull v) { return v ^ 0x8000000080000000ULL; }

// pad every 16 -> conflict-free remap phases
__device__ __forceinline__ int pidx(int i) { return i + (i >> 4); }

// 16 packed amps (2 batch elems per lane). Local bit j <-> wire (wbase - j).
// 8 coefficient packs per gate; Q-negation via XOR on the alu pipe.
__device__ __forceinline__ void apply_group(ull ar[16], ull ai[16],
                                            const float4 (*__restrict__ Usm)[2],
                                            int bg, int wbase)
{
#pragma unroll
    for (int j = 0; j < 4; j++) {
        float4 ua = Usm[bg + (wbase - j)][0];  // u00r,u00i,u01r,u01i
        float4 ub = Usm[bg + (wbase - j)][1];  // u10r,u10i,u11r,u11i
        ull A0r = pk(ua.x, ua.x), A0i = pk(ua.y, ua.y);
        ull A1r = pk(ua.z, ua.z), A1i = pk(ua.w, ua.w);
        ull B0r = pk(ub.x, ub.x), B0i = pk(ub.y, ub.y);
        ull B1r = pk(ub.z, ub.z), B1i = pk(ub.w, ub.w);
#pragma unroll
        for (int p = 0; p < 8; p++) {
            int k0 = ((p >> j) << (j + 1)) | (p & ((1 << j) - 1));
            int k1 = k0 | (1 << j);
            ull R0 = ar[k0], Q0 = ai[k0], R1 = ar[k1], Q1 = ai[k1];
            ull Q0n = neg2(Q0), Q1n = neg2(Q1);
            ar[k0] = fma2(A0r, R0, fma2(A0i, Q0n, fma2(A1r, R1, mul2(A1i, Q1n))));
            ai[k0] = fma2(A0r, Q0, fma2(A0i, R0,  fma2(A1r, Q1, mul2(A1i, R1))));
            ar[k1] = fma2(B0r, R0, fma2(B0i, Q0n, fma2(B1r, R1, mul2(B1i, Q1n))));
            ai[k1] = fma2(B0r, Q0, fma2(B0i, R0,  fma2(B1r, Q1, mul2(B1i, R1))));
        }
    }
}

__global__ __launch_bounds__(NT, 2)
void qsim_kernel(const float* __restrict__ state,
                 const float* __restrict__ weights,
                 const float* __restrict__ head_w,
                 const float* __restrict__ head_b,
                 float* __restrict__ out)
{
    extern __shared__ ulonglong2 buf[];    // [PADDED] {re_pack, im_pack}
    __shared__ float4 Usm[NL * NW][2];
    __shared__ float hw[NW];
    __shared__ ull warpsum[NT / 32];

    const int tid = threadIdx.x;
    const int b = blockIdx.x;  // handles batch rows 2b, 2b+1

    // ---- gate matrices U = RZ(c) RY(b) RX(a) ----
    if (tid < NL * NW) {
        float a = weights[tid * 3 + 0];
        float bb = weights[tid * 3 + 1];
        float c = weights[tid * 3 + 2];
        float sa, ca, sb, cb, sc, cc;
        sincosf(0.5f * a, &sa, &ca);
        sincosf(0.5f * bb, &sb, &cb);
        sincosf(0.5f * c, &sc, &cc);
        float m00r = cb * ca, m00i = sb * sa;
        float m01r = -sb * ca, m01i = -cb * sa;
        float m10r = sb * ca, m10i = -cb * sa;
        float m11r = cb * ca, m11i = -sb * sa;
        float4 uA, uB;
        uA.x = m00r * cc + m00i * sc;  uA.y = m00i * cc - m00r * sc;
        uA.z = m01r * cc + m01i * sc;  uA.w = m01i * cc - m01r * sc;
        uB.x = m10r * cc - m10i * sc;  uB.y = m10i * cc + m10r * sc;
        uB.z = m11r * cc - m11i * sc;  uB.w = m11i * cc + m11r * sc;
        Usm[tid][0] = uA;
        Usm[tid][1] = uB;
    }
    if (tid < NW) hw[tid] = head_w[tid];

    // ---- load two batch rows, pack into lanes (mapping A: i = (tid<<4)|k) ----
    ull ar[16], ai[16];
    const float4* s0 = (const float4*)(state + (size_t)(2 * b) * DIM);
    const float4* s1 = (const float4*)(state + (size_t)(2 * b + 1) * DIM);
#pragma unroll
    for (int q = 0; q < 4; q++) {
        float4 v0 = s0[tid * 4 + q];
        float4 v1 = s1[tid * 4 + q];
        ar[4 * q + 0] = pk(v0.x, v1.x);
        ar[4 * q + 1] = pk(v0.y, v1.y);
        ar[4 * q + 2] = pk(v0.z, v1.z);
        ar[4 * q + 3] = pk(v0.w, v1.w);
        ai[4 * q + 0] = 0ULL; ai[4 * q + 1] = 0ULL;
        ai[4 * q + 2] = 0ULL; ai[4 * q + 3] = 0ULL;
    }
    __syncthreads();  // Usm / hw ready

    for (int l = 0; l < NL; l++) {
        const int bg = l * NW;

        // group A: index bits 0-3 local -> wires 11..8
        apply_group(ar, ai, Usm, bg, 11);

        // remap A -> B (128-bit SMEM ops)
        __syncthreads();
#pragma unroll
        for (int k = 0; k < 16; k++) {
            buf[tid * 17 + k] = make_ulonglong2(ar[k], ai[k]);  // pidx((tid<<4)|k)
        }
        __syncthreads();
#pragma unroll
        for (int k = 0; k < 16; k++) {
            int i = ((tid >> 4) << 8) | (k << 4) | (tid & 15);
            ulonglong2 v = buf[pidx(i)];
            ar[k] = v.x; ai[k] = v.y;
        }

        // group B: index bits 4-7 local -> wires 7..4
        apply_group(ar, ai, Usm, bg, 7);

        // remap B -> C
        __syncthreads();
#pragma unroll
        for (int k = 0; k < 16; k++) {
            int i = ((tid >> 4) << 8) | (k << 4) | (tid & 15);
            buf[pidx(i)] = make_ulonglong2(ar[k], ai[k]);
        }
        __syncthreads();
#pragma unroll
        for (int k = 0; k < 16; k++) {
            int i = (k << 8) | tid;
            ulonglong2 v = buf[pidx(i)];
            ar[k] = v.x; ai[k] = v.y;
        }

        // group C: index bits 8-11 local -> wires 3..0
        apply_group(ar, ai, Usm, bg, 3);

        // layer boundary: remap C -> A fused with CNOT-chain perm
        // psi_new[y] = psi_old[y ^ (y>>1)]
        if (l < NL - 1) {
            __syncthreads();
#pragma unroll
            for (int k = 0; k < 16; k++) {
                int i = (k << 8) | tid;
                buf[pidx(i)] = make_ulonglong2(ar[k], ai[k]);
            }
            __syncthreads();
#pragma unroll
            for (int k = 0; k < 16; k++) {
                int y = (tid << 4) | k;
                int src = y ^ (y >> 1);
                ulonglong2 v = buf[pidx(src)];
                ar[k] = v.x; ai[k] = v.y;
            }
        }
    }

    // ---- measurement (mapping C), last CNOT perm folded into weights ----
    // out = sum_x |psi[x]|^2 * c(prefixXOR(x)) + bias ; x = (k<<8)|tid
    int m8 = tid;
    m8 ^= m8 >> 1; m8 ^= m8 >> 2; m8 ^= m8 >> 4;  // suffix-XOR over 8 bits
    float c_low = 0.f;
#pragma unroll
    for (int w = 4; w < 12; w++) {
        c_low += ((m8 >> (11 - w)) & 1) ? -hw[w] : hw[w];
    }
    ull acc2 = 0ULL;
#pragma unroll
    for (int k = 0; k < 16; k++) {
        int g4 = k;
        g4 ^= g4 >> 1; g4 ^= g4 >> 2;  // suffix-XOR over 4 bits
        float c_high = 0.f;
#pragma unroll
        for (int w = 0; w < 4; w++) {
            c_high += ((g4 >> (3 - w)) & 1) ? -hw[w] : hw[w];
        }
        float c = c_high + ((g4 & 1) ? -c_low : c_low);
        ull pr2 = fma2(ar[k], ar[k], mul2(ai[k], ai[k]));  // |psi|^2 both lanes
        acc2 = fma2(pr2, pk(c, c), acc2);
    }
#pragma unroll
    for (int o = 16; o > 0; o >>= 1) {
        float lo, hi;
        unpk(acc2, lo, hi);
        lo += __shfl_xor_sync(0xffffffffu, lo, o);
        hi += __shfl_xor_sync(0xffffffffu, hi, o);
        acc2 = pk(lo, hi);
    }
    if ((tid & 31) == 0) warpsum[tid >> 5] = acc2;
    __syncthreads();
    if (tid == 0) {
        float slo = 0.f, shi = 0.f;
#pragma unroll
        for (int i = 0; i < NT / 32; i++) {
            float lo, hi;
            unpk(warpsum[i], lo, hi);
            slo += lo; shi += hi;
        }
        float bias = head_b[0];
        out[2 * b + 0] = slo + bias;
        out[2 * b + 1] = shi + bias;
    }
}

extern "C" void kernel_launch(void* const* d_in, const int* in_sizes, int n_in,
                              void* d_out, int out_size)
{
    const float* state   = (const float*)d_in[0];  // (512, 4096)
    const float* weights = (const float*)d_in[1];  // (3, 12, 3)
    const float* head_w  = (const float*)d_in[2];  // (1, 12)
    const float* head_b  = (const float*)d_in[3];  // (1,)
    float* out = (float*)d_out;                    // (512,)
    cudaFuncSetAttribute(qsim_kernel, cudaFuncAttributeMaxDynamicSharedMemorySize, DYN_SMEM);
    qsim_kernel<<<BATCH / 2, NT, DYN_SMEM>>>(state, weights, head_w, head_b, out);
}